// round 12
// baseline (speedup 1.0000x reference)
#include <cuda_runtime.h>

#define NB   32
#define NCDD 5
#define NHIS 100
#define NS   20
#define NL   3
#define NF   150
#define NK   18
#define NRD  256
#define NBC  (NB*NCDD)        // 160
#define NEMB (NS*NL*NF)       // 9000

typedef unsigned long long u64t;

// ---------------- scratch (no device allocs allowed) ----------------
__device__ int   g_sel[NBC*NK];                 // selected news ids (topk order)
__device__ float g_fusion[NBC*NL*NK*NS*NS];     // [n][l][k][s][t]
__device__ float g_pool1[NBC*32*6*6*6];         // [n][oc][d][h][w]
__device__ float g_feat[NBC*128];               // [n][oc*8+od*4+oh*2+ow]

// ================= Kernel A: attention + top-K ====================
__global__ void attn_topk_kernel(const int* __restrict__ cdd_id,
                                 const int* __restrict__ his_id,
                                 const float* __restrict__ repr)
{
    int bc = blockIdx.x;
    int b  = bc / NCDD;
    __shared__ float cv[NRD];
    __shared__ float av[NHIS];
    int tid = threadIdx.x;
    const float* crow = repr + cdd_id[bc] * NRD;
    #pragma unroll 1
    for (int i = tid; i < NRD; i += 128) cv[i] = crow[i];
    __syncthreads();
    int warp = tid >> 5, lane = tid & 31;
    #pragma unroll 1
    for (int h = warp; h < NHIS; h += 4) {
        const float* hrow = repr + his_id[b*NHIS + h] * NRD;
        float s = 0.f;
        #pragma unroll 1
        for (int j = lane; j < NRD; j += 32) s += cv[j] * hrow[j];
        s += __shfl_down_sync(0xffffffffu, s, 16);
        s += __shfl_down_sync(0xffffffffu, s, 8);
        s += __shfl_down_sync(0xffffffffu, s, 4);
        s += __shfl_down_sync(0xffffffffu, s, 2);
        s += __shfl_down_sync(0xffffffffu, s, 1);
        if (lane == 0) av[h] = s;
    }
    __syncthreads();
    // warp-parallel top-K selection (stable: ties -> smaller index)
    if (warp == 0) {
        #pragma unroll 1
        for (int k = 0; k < NK; k++) {
            float bv = -1e38f; int bi = 0x7fffffff;
            #pragma unroll 1
            for (int h = lane; h < NHIS; h += 32) {
                float v = av[h];
                if (v > bv) { bv = v; bi = h; }
            }
            #pragma unroll
            for (int o = 16; o > 0; o >>= 1) {
                float ov = __shfl_xor_sync(0xffffffffu, bv, o);
                int   oi = __shfl_xor_sync(0xffffffffu, bi, o);
                if (ov > bv || (ov == bv && oi < bi)) { bv = ov; bi = oi; }
            }
            if (lane == 0) {
                av[bi] = -1e38f;
                g_sel[bc*NK + k] = his_id[b*NHIS + bi];
            }
            __syncwarp();
        }
    }
}

// ================= Kernel B: fusion batched GEMM ====================
// fusion[bc,k,l,s,t] = sum_f cdd[s,l,f] * his[t,l,f] / sqrt(F)
// stored [n=bc][l][k][s][t] (conv1 NCDHW: channel=l, depth=k)
// Single-pass: full rows in smem, layout [l][f][s(pad22)] so b-pairs are
// contiguous -> LDS.64 + packed fma.rn.f32x2.
#define SP 22
__global__ void fusion_kernel(const int* __restrict__ cdd_id,
                              const float* __restrict__ emb)
{
    int k  = blockIdx.x;
    int bc = blockIdx.y;
    const float* arow = emb + cdd_id[bc] * NEMB;
    const float* brow = emb + g_sel[bc*NK + k] * NEMB;

    __shared__ __align__(8) float As[NL*NF*SP];   // [(l*150+f)*22 + s]
    __shared__ __align__(8) float Bs[NL*NF*SP];

    int tid = threadIdx.x;     // 160

    #pragma unroll 1
    for (int i = tid; i < NEMB; i += 160) {
        int s = i / (NL*NF);
        int r = i % (NL*NF);        // l*150+f
        As[r*SP + s] = arow[i];
        Bs[r*SP + s] = brow[i];
    }
    __syncthreads();

    if (tid < 75) {
        int l = tid / 25, q = tid % 25;
        int st = (q / 5) * 4, tt = (q % 5) * 4;

        const float* ap = &As[l*NF*SP + st];                       // ap[f*22+i]
        const u64t*  bp = reinterpret_cast<const u64t*>(&Bs[l*NF*SP + tt]);

        u64t acc2[8];
        #pragma unroll
        for (int i = 0; i < 8; i++) acc2[i] = 0ULL;

        #pragma unroll 2
        for (int f = 0; f < NF; f++) {
            u64t b01 = bp[f*11];
            u64t b23 = bp[f*11 + 1];
            #pragma unroll
            for (int i = 0; i < 4; i++) {
                float a = ap[f*SP + i];
                u64t av2;
                asm("mov.b64 %0, {%1, %1};" : "=l"(av2) : "f"(a));
                asm("fma.rn.f32x2 %0, %1, %2, %3;"
                    : "=l"(acc2[i*2])     : "l"(av2), "l"(b01), "l"(acc2[i*2]));
                asm("fma.rn.f32x2 %0, %1, %2, %3;"
                    : "=l"(acc2[i*2+1])   : "l"(av2), "l"(b23), "l"(acc2[i*2+1]));
            }
        }
        const float inv = 0.08164965809277261f;  // 1/sqrt(150)
        float* out = g_fusion + ((bc*NL + l)*NK + k)*(NS*NS);
        #pragma unroll
        for (int i = 0; i < 4; i++) {
            float v0, v1, v2, v3;
            asm("mov.b64 {%0, %1}, %2;" : "=f"(v0), "=f"(v1) : "l"(acc2[i*2]));
            asm("mov.b64 {%0, %1}, %2;" : "=f"(v2), "=f"(v3) : "l"(acc2[i*2+1]));
            out[(st+i)*NS + tt + 0] = v0 * inv;
            out[(st+i)*NS + tt + 1] = v1 * inv;
            out[(st+i)*NS + tt + 2] = v2 * inv;
            out[(st+i)*NS + tt + 3] = v3 * inv;
        }
    }
}

// ============ Kernel C: conv1(3->32,3^3,pad1)+bias+ReLU+maxpool3 ============
// in  g_fusion [n][3][18][20][20] -> out g_pool1 [n][32][6][6][6]
// block = (od, n); 576 thr = 16 oc-pairs x 36 pooled (oh,ow); 2 oc per thread.
// Packed f32x2 FMA: oc-pair accumulators, weights repacked [tap][oc].
__global__ void conv1_pool_kernel(const float* __restrict__ w1,
                                  const float* __restrict__ b1)
{
    int od = blockIdx.x;   // 0..5
    int n  = blockIdx.y;   // 0..159

    __shared__ float in_s[5*3*22*22];             // zero halo; d halo = zero slabs
    __shared__ __align__(16) float ws2[81*32];    // [tap tf=ic*27+kd*9+t][oc]
    __shared__ float bs[32];

    int tid = threadIdx.x;

    #pragma unroll 1
    for (int i = tid; i < 5*3*22*22; i += 576) in_s[i] = 0.f;
    #pragma unroll 1
    for (int i = tid; i < 32*81; i += 576) {
        int oc = i / 81, tf = i % 81;
        ws2[tf*32 + oc] = w1[i];
    }
    if (tid < 32) bs[tid] = b1[tid];
    __syncthreads();

    #pragma unroll 1
    for (int idx = tid; idx < 5*3*400; idx += 576) {
        int slab = idx / 1200;
        int r    = idx % 1200;
        int ic   = r / 400;
        int p    = r % 400;
        int d    = od*3 - 1 + slab;
        if (d >= 0 && d < 18)
            in_s[((slab*3 + ic)*22 + 1 + p/20)*22 + 1 + p%20] =
                g_fusion[((n*3 + ic)*18 + d)*400 + p];
    }
    __syncthreads();

    int op  = tid / 36;         // 0..15
    int pos = tid % 36;
    int oh  = pos / 6, ow = pos % 6;
    int oc0 = op*2;

    float m0 = 0.f, m1 = 0.f;   // relu outputs >= 0

    #pragma unroll 1
    for (int dd = 0; dd < 3; dd++) {
        u64t acc2[9];
        #pragma unroll
        for (int i = 0; i < 9; i++) acc2[i] = 0ULL;

        #pragma unroll 1
        for (int ic = 0; ic < 3; ic++) {
            #pragma unroll 1
            for (int kd = 0; kd < 3; kd++) {
                const float* base = &in_s[(((dd + kd)*3 + ic)*22 + oh*3)*22 + ow*3];
                u64t pv[25];
                #pragma unroll
                for (int r = 0; r < 5; r++)
                    #pragma unroll
                    for (int c = 0; c < 5; c++) {
                        float v = base[r*22 + c];
                        asm("mov.b64 %0, {%1, %1};" : "=l"(pv[r*5 + c]) : "f"(v));
                    }

                const u64t* wp = reinterpret_cast<const u64t*>(
                    &ws2[(ic*27 + kd*9)*32 + oc0]);
                u64t wv[9];
                #pragma unroll
                for (int t = 0; t < 9; t++) wv[t] = wp[t*16];  // stride 32 floats

                #pragma unroll
                for (int hh = 0; hh < 3; hh++)
                    #pragma unroll
                    for (int ww = 0; ww < 3; ww++) {
                        u64t s = acc2[hh*3 + ww];
                        #pragma unroll
                        for (int kh = 0; kh < 3; kh++)
                            #pragma unroll
                            for (int kw = 0; kw < 3; kw++)
                                asm("fma.rn.f32x2 %0, %1, %2, %3;"
                                    : "=l"(s)
                                    : "l"(wv[kh*3 + kw]),
                                      "l"(pv[(hh+kh)*5 + (ww+kw)]),
                                      "l"(s));
                        acc2[hh*3 + ww] = s;
                    }
            }
        }
        float b0v = bs[oc0], b1v = bs[oc0 + 1];
        #pragma unroll
        for (int i = 0; i < 9; i++) {
            float v0, v1;
            asm("mov.b64 {%0, %1}, %2;" : "=f"(v0), "=f"(v1) : "l"(acc2[i]));
            v0 += b0v; if (v0 < 0.f) v0 = 0.f; if (v0 > m0) m0 = v0;
            v1 += b1v; if (v1 < 0.f) v1 = 0.f; if (v1 > m1) m1 = v1;
        }
    }
    g_pool1[((n*32 + oc0)*6 + od)*36 + oh*6 + ow]     = m0;
    g_pool1[((n*32 + oc0 + 1)*6 + od)*36 + oh*6 + ow] = m1;
}

// ============ Kernel D: conv2(32->16)+bias+ReLU+maxpool3 ============
// in g_pool1 [n][32][6][6][6] -> out g_feat [n][128]
// grid (2 ocg, n); 576 thr = 8oc x 8pos x 3dd x 3icp (ic split 3-way).
// Conflict-free padded smem; partials combined via psum.
#define D_STR 68
#define W_STR 872
__global__ void conv2_pool_kernel(const float* __restrict__ w2,
                                  const float* __restrict__ b2)
{
    int ocg = blockIdx.x;    // 0..1
    int n   = blockIdx.y;    // 0..159

    __shared__ float in2[32*6*D_STR];   // [ic][d] slabs of 8x8 (h,w halo), pad 4
    __shared__ float wsm[8*W_STR];      // [ocl] stride 872 (= 864 + 8 pad)
    __shared__ float psum[2*192*9];     // partials from icp 0,1
    __shared__ float red[192];
    int tid = threadIdx.x;              // 576

    #pragma unroll 1
    for (int i = tid; i < 32*6*D_STR; i += 576) in2[i] = 0.f;
    #pragma unroll 1
    for (int i = tid; i < 8*864; i += 576) {
        int ocl = i / 864;
        int r   = i % 864;
        wsm[ocl*W_STR + r] = w2[(ocg*8 + ocl)*864 + r];
    }
    __syncthreads();
    #pragma unroll 1
    for (int idx = tid; idx < 32*216; idx += 576) {
        int ic = idx / 216;
        int r  = idx % 216;
        int d  = r / 36;
        int h  = (r % 36) / 6;
        int w  = r % 6;
        in2[(ic*6 + d)*D_STR + (h + 1)*8 + w + 1] = g_pool1[n*32*216 + idx];
    }
    __syncthreads();

    // tid = t3*3 + icp ; t3 = t4*3 + dd ; t4 = ocl*8 + pos
    int icp = tid % 3;
    int t3  = tid / 3;          // 0..191
    int dd  = t3 % 3;
    int t4  = t3 / 3;           // 0..63
    int pos = t4 & 7;
    int ocl = t4 >> 3;          // 0..7
    int od  = (pos >> 2) & 1, oh = (pos >> 1) & 1, ow = pos & 1;

    float acc[9];
    #pragma unroll
    for (int i = 0; i < 9; i++) acc[i] = 0.f;

    #pragma unroll 1
    for (int ic = icp; ic < 32; ic += 3) {
        #pragma unroll 1
        for (int kd = 0; kd < 3; kd++) {
            int d = od*3 + dd + kd - 1;
            if (d < 0 || d > 5) continue;
            const float* wbase = &wsm[ocl*W_STR + ic*27 + kd*9];
            float wr[9];
            #pragma unroll
            for (int t = 0; t < 9; t++) wr[t] = wbase[t];
            const float* base = &in2[(ic*6 + d)*D_STR + (oh*3)*8 + ow*3];
            float p[25];
            #pragma unroll
            for (int r = 0; r < 5; r++)
                #pragma unroll
                for (int c = 0; c < 5; c++)
                    p[r*5 + c] = base[r*8 + c];
            #pragma unroll
            for (int hh = 0; hh < 3; hh++)
                #pragma unroll
                for (int ww = 0; ww < 3; ww++) {
                    float s = acc[hh*3 + ww];
                    #pragma unroll
                    for (int kh = 0; kh < 3; kh++)
                        #pragma unroll
                        for (int kw = 0; kw < 3; kw++)
                            s = fmaf(wr[kh*3 + kw], p[(hh+kh)*5 + (ww+kw)], s);
                    acc[hh*3 + ww] = s;
                }
        }
    }

    if (icp < 2) {
        #pragma unroll
        for (int i = 0; i < 9; i++) psum[(icp*192 + t3)*9 + i] = acc[i];
    }
    __syncthreads();
    if (icp == 2) {
        float bias = b2[ocg*8 + ocl];
        float m = 0.f;
        #pragma unroll
        for (int i = 0; i < 9; i++) {
            float v = acc[i] + psum[t3*9 + i] + psum[(192 + t3)*9 + i] + bias;
            if (v < 0.f) v = 0.f;
            if (v > m) m = v;
        }
        red[t3] = m;
    }
    __syncthreads();
    if (icp == 2 && dd == 0) {
        float f = red[t3];
        if (red[t3+1] > f) f = red[t3+1];
        if (red[t3+2] > f) f = red[t3+2];
        g_feat[n*128 + (ocg*8 + ocl)*8 + od*4 + oh*2 + ow] = f;
    }
}

// ============ Kernel E: LTR score + log_softmax over CDD ============
// 160 threads (5 warps). Warp-per-candidate coalesced dot products.
__global__ void score_kernel(const float* __restrict__ lw,
                             const float* __restrict__ lb,
                             float* __restrict__ out)
{
    __shared__ float lws[128];
    __shared__ float sc[NBC];
    int tid  = threadIdx.x;
    int warp = tid >> 5, lane = tid & 31;
    if (tid < 128) lws[tid] = lw[tid];
    __syncthreads();

    #pragma unroll 1
    for (int c = warp; c < NBC; c += 5) {
        const float* f = g_feat + c*128;
        float s = 0.f;
        #pragma unroll
        for (int j = 0; j < 4; j++)
            s = fmaf(f[j*32 + lane], lws[j*32 + lane], s);
        s += __shfl_down_sync(0xffffffffu, s, 16);
        s += __shfl_down_sync(0xffffffffu, s, 8);
        s += __shfl_down_sync(0xffffffffu, s, 4);
        s += __shfl_down_sync(0xffffffffu, s, 2);
        s += __shfl_down_sync(0xffffffffu, s, 1);
        if (lane == 0) sc[c] = s + lb[0];
    }
    __syncthreads();

    if (tid < NBC) {
        int b = tid / NCDD;
        float m = -1e38f;
        #pragma unroll 1
        for (int c = 0; c < NCDD; c++) { float v = sc[b*NCDD + c]; if (v > m) m = v; }
        float sum = 0.f;
        #pragma unroll 1
        for (int c = 0; c < NCDD; c++) sum += expf(sc[b*NCDD + c] - m);
        out[tid] = sc[tid] - m - logf(sum);
    }
}

// =================================================================
extern "C" void kernel_launch(void* const* d_in, const int* in_sizes, int n_in,
                              void* d_out, int out_size)
{
    const int*   cdd_id = (const int*)d_in[0];
    const int*   his_id = (const int*)d_in[1];
    const float* repr   = (const float*)d_in[2];
    const float* emb    = (const float*)d_in[3];
    const float* w1     = (const float*)d_in[4];
    const float* b1     = (const float*)d_in[5];
    const float* w2     = (const float*)d_in[6];
    const float* b2     = (const float*)d_in[7];
    const float* lw     = (const float*)d_in[8];
    const float* lb     = (const float*)d_in[9];

    attn_topk_kernel<<<NBC, 128>>>(cdd_id, his_id, repr);
    fusion_kernel<<<dim3(NK, NBC), 160>>>(cdd_id, emb);
    conv1_pool_kernel<<<dim3(6, NBC), 576>>>(w1, b1);
    conv2_pool_kernel<<<dim3(2, NBC), 576>>>(w2, b2);
    score_kernel<<<1, NBC>>>(lw, lb, (float*)d_out);
}

// round 13
// speedup vs baseline: 1.1538x; 1.1538x over previous
#include <cuda_runtime.h>

#define NB   32
#define NCDD 5
#define NHIS 100
#define NS   20
#define NL   3
#define NF   150
#define NK   18
#define NRD  256
#define NBC  (NB*NCDD)        // 160
#define NEMB (NS*NL*NF)       // 9000

typedef unsigned long long u64t;

// ---------------- scratch (no device allocs allowed) ----------------
__device__ int   g_sel[NBC*NK];                 // selected news ids (topk order)
__device__ float g_fusion[NBC*NL*NK*NS*NS];     // [n][l][k][s][t]
__device__ float g_pool1[NBC*32*6*6*6];         // [n][oc][d][h][w]
__device__ float g_feat[NBC*128];               // [n][oc*8+od*4+oh*2+ow]

// ================= Kernel A: attention + top-K ====================
__global__ void attn_topk_kernel(const int* __restrict__ cdd_id,
                                 const int* __restrict__ his_id,
                                 const float* __restrict__ repr)
{
    int bc = blockIdx.x;
    int b  = bc / NCDD;
    __shared__ float cv[NRD];
    __shared__ float av[NHIS];
    int tid = threadIdx.x;
    const float* crow = repr + cdd_id[bc] * NRD;
    #pragma unroll 1
    for (int i = tid; i < NRD; i += 128) cv[i] = crow[i];
    __syncthreads();
    int warp = tid >> 5, lane = tid & 31;
    #pragma unroll 1
    for (int h = warp; h < NHIS; h += 4) {
        const float* hrow = repr + his_id[b*NHIS + h] * NRD;
        float s = 0.f;
        #pragma unroll 1
        for (int j = lane; j < NRD; j += 32) s += cv[j] * hrow[j];
        s += __shfl_down_sync(0xffffffffu, s, 16);
        s += __shfl_down_sync(0xffffffffu, s, 8);
        s += __shfl_down_sync(0xffffffffu, s, 4);
        s += __shfl_down_sync(0xffffffffu, s, 2);
        s += __shfl_down_sync(0xffffffffu, s, 1);
        if (lane == 0) av[h] = s;
    }
    __syncthreads();
    // warp-parallel top-K selection (stable: ties -> smaller index)
    if (warp == 0) {
        #pragma unroll 1
        for (int k = 0; k < NK; k++) {
            float bv = -1e38f; int bi = 0x7fffffff;
            #pragma unroll 1
            for (int h = lane; h < NHIS; h += 32) {
                float v = av[h];
                if (v > bv) { bv = v; bi = h; }
            }
            #pragma unroll
            for (int o = 16; o > 0; o >>= 1) {
                float ov = __shfl_xor_sync(0xffffffffu, bv, o);
                int   oi = __shfl_xor_sync(0xffffffffu, bi, o);
                if (ov > bv || (ov == bv && oi < bi)) { bv = ov; bi = oi; }
            }
            if (lane == 0) {
                av[bi] = -1e38f;
                g_sel[bc*NK + k] = his_id[b*NHIS + bi];
            }
            __syncwarp();
        }
    }
}

// ================= Kernel B: fusion batched GEMM ====================
// fusion[bc,k,l,s,t] = sum_f cdd[s,l,f] * his[t,l,f] / sqrt(F)
// stored [n=bc][l][k][s][t] (conv1 NCDHW: channel=l, depth=k)
#define FC 50
#define FCP 52
__global__ void fusion_kernel(const int* __restrict__ cdd_id,
                              const float* __restrict__ emb)
{
    int k  = blockIdx.x;
    int bc = blockIdx.y;
    const float* arow = emb + cdd_id[bc] * NEMB;
    const float* brow = emb + g_sel[bc*NK + k] * NEMB;

    __shared__ float As[NL*NS*FCP];
    __shared__ float Bs[NL*NS*FCP];

    int tid = threadIdx.x;
    int l = tid / 25, q = tid % 25;
    int st = (q / 5) * 4, tt = (q % 5) * 4;

    float acc[16];
    #pragma unroll
    for (int i = 0; i < 16; i++) acc[i] = 0.f;

    #pragma unroll 1
    for (int fc = 0; fc < NF; fc += FC) {
        #pragma unroll 1
        for (int idx = tid; idx < NL*NS*FC; idx += 128) {
            int ll = idx / (NS*FC);
            int r  = idx % (NS*FC);
            int s  = r / FC;
            int f  = r % FC;
            int off = s*(NL*NF) + ll*NF + fc + f;
            As[(ll*NS + s)*FCP + f] = arow[off];
            Bs[(ll*NS + s)*FCP + f] = brow[off];
        }
        __syncthreads();
        if (tid < 75) {
            const float* ap = &As[(l*NS + st)*FCP];
            const float* bp = &Bs[(l*NS + tt)*FCP];
            #pragma unroll 2
            for (int f = 0; f < FC; f++) {
                float a0 = ap[f], a1 = ap[FCP + f];
                float a2 = ap[2*FCP + f], a3 = ap[3*FCP + f];
                float b0 = bp[f], b1 = bp[FCP + f];
                float b2 = bp[2*FCP + f], b3 = bp[3*FCP + f];
                acc[0]  = fmaf(a0,b0,acc[0]);  acc[1]  = fmaf(a0,b1,acc[1]);
                acc[2]  = fmaf(a0,b2,acc[2]);  acc[3]  = fmaf(a0,b3,acc[3]);
                acc[4]  = fmaf(a1,b0,acc[4]);  acc[5]  = fmaf(a1,b1,acc[5]);
                acc[6]  = fmaf(a1,b2,acc[6]);  acc[7]  = fmaf(a1,b3,acc[7]);
                acc[8]  = fmaf(a2,b0,acc[8]);  acc[9]  = fmaf(a2,b1,acc[9]);
                acc[10] = fmaf(a2,b2,acc[10]); acc[11] = fmaf(a2,b3,acc[11]);
                acc[12] = fmaf(a3,b0,acc[12]); acc[13] = fmaf(a3,b1,acc[13]);
                acc[14] = fmaf(a3,b2,acc[14]); acc[15] = fmaf(a3,b3,acc[15]);
            }
        }
        __syncthreads();
    }
    if (tid < 75) {
        const float inv = 0.08164965809277261f;  // 1/sqrt(150)
        float* out = g_fusion + ((bc*NL + l)*NK + k)*(NS*NS);
        #pragma unroll 1
        for (int i = 0; i < 4; i++)
            #pragma unroll 1
            for (int j = 0; j < 4; j++)
                out[(st+i)*NS + (tt+j)] = acc[i*4+j] * inv;
    }
}

// ============ Kernel C: conv1(3->32,3^3,pad1)+bias+ReLU+maxpool3 ============
// in  g_fusion [n][3][18][20][20] -> out g_pool1 [n][32][6][6][6]
// Launched as TWO halves (od_base 0 and 3) so ncu's capture slot lands on it.
// block = (odl, n); 576 thr = 16 oc-pairs x 36 pooled (oh,ow); 2 oc per thread.
__global__ void conv1_pool_kernel(const float* __restrict__ w1,
                                  const float* __restrict__ b1,
                                  int od_base)
{
    int od = od_base + blockIdx.x;   // 0..2 or 3..5
    int n  = blockIdx.y;             // 0..159

    __shared__ float in_s[5*3*22*22];   // zero halo in h,w; d halo = zero slabs
    __shared__ float ws[32*81];         // [oc][ic*27+kd*9+kh*3+kw]
    __shared__ float bs[32];

    int tid = threadIdx.x;

    #pragma unroll 1
    for (int i = tid; i < 5*3*22*22; i += 576) in_s[i] = 0.f;
    #pragma unroll 1
    for (int i = tid; i < 32*81; i += 576) ws[i] = w1[i];
    if (tid < 32) bs[tid] = b1[tid];
    __syncthreads();

    #pragma unroll 1
    for (int idx = tid; idx < 5*3*400; idx += 576) {
        int slab = idx / 1200;
        int r    = idx % 1200;
        int ic   = r / 400;
        int p    = r % 400;
        int d    = od*3 - 1 + slab;
        if (d >= 0 && d < 18)
            in_s[((slab*3 + ic)*22 + 1 + p/20)*22 + 1 + p%20] =
                g_fusion[((n*3 + ic)*18 + d)*400 + p];
    }
    __syncthreads();

    int op  = tid / 36;         // 0..15
    int pos = tid % 36;
    int oh  = pos / 6, ow = pos % 6;
    int oc0 = op*2, oc1 = op*2 + 1;

    float m0 = 0.f, m1 = 0.f;   // relu outputs >= 0

    #pragma unroll 1
    for (int dd = 0; dd < 3; dd++) {
        float acc0[9], acc1[9];
        #pragma unroll
        for (int i = 0; i < 9; i++) { acc0[i] = 0.f; acc1[i] = 0.f; }

        #pragma unroll 1
        for (int ic = 0; ic < 3; ic++) {
            #pragma unroll 1
            for (int kd = 0; kd < 3; kd++) {
                const float* base = &in_s[(((dd + kd)*3 + ic)*22 + oh*3)*22 + ow*3];
                float p[25];
                #pragma unroll
                for (int r = 0; r < 5; r++)
                    #pragma unroll
                    for (int c = 0; c < 5; c++)
                        p[r*5 + c] = base[r*22 + c];

                const float* wp0 = &ws[oc0*81 + ic*27 + kd*9];
                const float* wp1 = &ws[oc1*81 + ic*27 + kd*9];
                float wa[9], wb[9];
                #pragma unroll
                for (int t = 0; t < 9; t++) { wa[t] = wp0[t]; wb[t] = wp1[t]; }

                #pragma unroll
                for (int hh = 0; hh < 3; hh++)
                    #pragma unroll
                    for (int ww = 0; ww < 3; ww++) {
                        float s0 = acc0[hh*3 + ww];
                        float s1 = acc1[hh*3 + ww];
                        #pragma unroll
                        for (int kh = 0; kh < 3; kh++)
                            #pragma unroll
                            for (int kw = 0; kw < 3; kw++) {
                                float v = p[(hh+kh)*5 + (ww+kw)];
                                s0 = fmaf(wa[kh*3 + kw], v, s0);
                                s1 = fmaf(wb[kh*3 + kw], v, s1);
                            }
                        acc0[hh*3 + ww] = s0;
                        acc1[hh*3 + ww] = s1;
                    }
            }
        }
        float b0v = bs[oc0], b1v = bs[oc1];
        #pragma unroll
        for (int i = 0; i < 9; i++) {
            float v0 = acc0[i] + b0v; if (v0 < 0.f) v0 = 0.f; if (v0 > m0) m0 = v0;
            float v1 = acc1[i] + b1v; if (v1 < 0.f) v1 = 0.f; if (v1 > m1) m1 = v1;
        }
    }
    g_pool1[((n*32 + oc0)*6 + od)*36 + oh*6 + ow] = m0;
    g_pool1[((n*32 + oc1)*6 + od)*36 + oh*6 + ow] = m1;
}

// ============ Kernel D: conv2(32->16)+bias+ReLU+maxpool3 ============
// in g_pool1 [n][32][6][6][6] -> out g_feat [n][128]
// grid (2 ocg, n); 576 thr = 8oc x 8pos x 3dd x 3icp (ic split 3-way).
// Conflict-free padded smem; partials combined via psum.
#define D_STR 68
#define W_STR 872
__global__ void conv2_pool_kernel(const float* __restrict__ w2,
                                  const float* __restrict__ b2)
{
    int ocg = blockIdx.x;    // 0..1
    int n   = blockIdx.y;    // 0..159

    __shared__ float in2[32*6*D_STR];   // [ic][d] slabs of 8x8 (h,w halo), pad 4
    __shared__ float wsm[8*W_STR];      // [ocl] stride 872 (= 864 + 8 pad)
    __shared__ float psum[2*192*9];     // partials from icp 0,1
    __shared__ float red[192];
    int tid = threadIdx.x;              // 576

    #pragma unroll 1
    for (int i = tid; i < 32*6*D_STR; i += 576) in2[i] = 0.f;
    #pragma unroll 1
    for (int i = tid; i < 8*864; i += 576) {
        int ocl = i / 864;
        int r   = i % 864;
        wsm[ocl*W_STR + r] = w2[(ocg*8 + ocl)*864 + r];
    }
    __syncthreads();
    #pragma unroll 1
    for (int idx = tid; idx < 32*216; idx += 576) {
        int ic = idx / 216;
        int r  = idx % 216;
        int d  = r / 36;
        int h  = (r % 36) / 6;
        int w  = r % 6;
        in2[(ic*6 + d)*D_STR + (h + 1)*8 + w + 1] = g_pool1[n*32*216 + idx];
    }
    __syncthreads();

    // tid = t3*3 + icp ; t3 = t4*3 + dd ; t4 = ocl*8 + pos
    int icp = tid % 3;
    int t3  = tid / 3;          // 0..191
    int dd  = t3 % 3;
    int t4  = t3 / 3;           // 0..63
    int pos = t4 & 7;
    int ocl = t4 >> 3;          // 0..7
    int od  = (pos >> 2) & 1, oh = (pos >> 1) & 1, ow = pos & 1;

    float acc[9];
    #pragma unroll
    for (int i = 0; i < 9; i++) acc[i] = 0.f;

    #pragma unroll 1
    for (int ic = icp; ic < 32; ic += 3) {
        #pragma unroll 1
        for (int kd = 0; kd < 3; kd++) {
            int d = od*3 + dd + kd - 1;
            if (d < 0 || d > 5) continue;
            const float* wbase = &wsm[ocl*W_STR + ic*27 + kd*9];
            float wr[9];
            #pragma unroll
            for (int t = 0; t < 9; t++) wr[t] = wbase[t];
            const float* base = &in2[(ic*6 + d)*D_STR + (oh*3)*8 + ow*3];
            float p[25];
            #pragma unroll
            for (int r = 0; r < 5; r++)
                #pragma unroll
                for (int c = 0; c < 5; c++)
                    p[r*5 + c] = base[r*8 + c];
            #pragma unroll
            for (int hh = 0; hh < 3; hh++)
                #pragma unroll
                for (int ww = 0; ww < 3; ww++) {
                    float s = acc[hh*3 + ww];
                    #pragma unroll
                    for (int kh = 0; kh < 3; kh++)
                        #pragma unroll
                        for (int kw = 0; kw < 3; kw++)
                            s = fmaf(wr[kh*3 + kw], p[(hh+kh)*5 + (ww+kw)], s);
                    acc[hh*3 + ww] = s;
                }
        }
    }

    if (icp < 2) {
        #pragma unroll
        for (int i = 0; i < 9; i++) psum[(icp*192 + t3)*9 + i] = acc[i];
    }
    __syncthreads();
    if (icp == 2) {
        float bias = b2[ocg*8 + ocl];
        float m = 0.f;
        #pragma unroll
        for (int i = 0; i < 9; i++) {
            float v = acc[i] + psum[t3*9 + i] + psum[(192 + t3)*9 + i] + bias;
            if (v < 0.f) v = 0.f;
            if (v > m) m = v;
        }
        red[t3] = m;
    }
    __syncthreads();
    if (icp == 2 && dd == 0) {
        float f = red[t3];
        if (red[t3+1] > f) f = red[t3+1];
        if (red[t3+2] > f) f = red[t3+2];
        g_feat[n*128 + (ocg*8 + ocl)*8 + od*4 + oh*2 + ow] = f;
    }
}

// ============ Kernel E: LTR score + log_softmax over CDD ============
// 160 threads (5 warps). Warp-per-candidate coalesced dot products.
__global__ void score_kernel(const float* __restrict__ lw,
                             const float* __restrict__ lb,
                             float* __restrict__ out)
{
    __shared__ float lws[128];
    __shared__ float sc[NBC];
    int tid  = threadIdx.x;
    int warp = tid >> 5, lane = tid & 31;
    if (tid < 128) lws[tid] = lw[tid];
    __syncthreads();

    #pragma unroll 1
    for (int c = warp; c < NBC; c += 5) {
        const float* f = g_feat + c*128;
        float s = 0.f;
        #pragma unroll
        for (int j = 0; j < 4; j++)
            s = fmaf(f[j*32 + lane], lws[j*32 + lane], s);
        s += __shfl_down_sync(0xffffffffu, s, 16);
        s += __shfl_down_sync(0xffffffffu, s, 8);
        s += __shfl_down_sync(0xffffffffu, s, 4);
        s += __shfl_down_sync(0xffffffffu, s, 2);
        s += __shfl_down_sync(0xffffffffu, s, 1);
        if (lane == 0) sc[c] = s + lb[0];
    }
    __syncthreads();

    if (tid < NBC) {
        int b = tid / NCDD;
        float m = -1e38f;
        #pragma unroll 1
        for (int c = 0; c < NCDD; c++) { float v = sc[b*NCDD + c]; if (v > m) m = v; }
        float sum = 0.f;
        #pragma unroll 1
        for (int c = 0; c < NCDD; c++) sum += expf(sc[b*NCDD + c] - m);
        out[tid] = sc[tid] - m - logf(sum);
    }
}

// =================================================================
extern "C" void kernel_launch(void* const* d_in, const int* in_sizes, int n_in,
                              void* d_out, int out_size)
{
    const int*   cdd_id = (const int*)d_in[0];
    const int*   his_id = (const int*)d_in[1];
    const float* repr   = (const float*)d_in[2];
    const float* emb    = (const float*)d_in[3];
    const float* w1     = (const float*)d_in[4];
    const float* b1     = (const float*)d_in[5];
    const float* w2     = (const float*)d_in[6];
    const float* b2     = (const float*)d_in[7];
    const float* lw     = (const float*)d_in[8];
    const float* lb     = (const float*)d_in[9];

    attn_topk_kernel<<<NBC, 128>>>(cdd_id, his_id, repr);
    fusion_kernel<<<dim3(NK, NBC), 128>>>(cdd_id, emb);
    conv1_pool_kernel<<<dim3(3, NBC), 576>>>(w1, b1, 0);
    conv1_pool_kernel<<<dim3(3, NBC), 576>>>(w1, b1, 3);
    conv2_pool_kernel<<<dim3(2, NBC), 576>>>(w2, b2);
    score_kernel<<<1, NBC>>>(lw, lb, (float*)d_out);
}

// round 14
// speedup vs baseline: 1.2071x; 1.0461x over previous
#include <cuda_runtime.h>

#define NB   32
#define NCDD 5
#define NHIS 100
#define NS   20
#define NL   3
#define NF   150
#define NK   18
#define NRD  256
#define NBC  (NB*NCDD)        // 160
#define NEMB (NS*NL*NF)       // 9000

typedef unsigned long long u64t;

// ---------------- scratch (no device allocs allowed) ----------------
__device__ int   g_sel[NBC*NK];                 // selected news ids (topk order)
__device__ float g_fusion[NBC*NL*NK*NS*NS];     // [n][l][k][s][t]
__device__ float g_pool1[NBC*32*6*6*6];         // [n][oc][d][h][w]
__device__ float g_feat[NBC*128];               // [n][oc*8+od*4+oh*2+ow]

// ================= Kernel A: attention + top-K ====================
__global__ void attn_topk_kernel(const int* __restrict__ cdd_id,
                                 const int* __restrict__ his_id,
                                 const float* __restrict__ repr)
{
    int bc = blockIdx.x;
    int b  = bc / NCDD;
    __shared__ float cv[NRD];
    __shared__ float av[NHIS];
    int tid = threadIdx.x;
    const float* crow = repr + cdd_id[bc] * NRD;
    #pragma unroll 1
    for (int i = tid; i < NRD; i += 128) cv[i] = crow[i];
    __syncthreads();
    int warp = tid >> 5, lane = tid & 31;
    #pragma unroll 1
    for (int h = warp; h < NHIS; h += 4) {
        const float* hrow = repr + his_id[b*NHIS + h] * NRD;
        float s = 0.f;
        #pragma unroll 1
        for (int j = lane; j < NRD; j += 32) s += cv[j] * hrow[j];
        s += __shfl_down_sync(0xffffffffu, s, 16);
        s += __shfl_down_sync(0xffffffffu, s, 8);
        s += __shfl_down_sync(0xffffffffu, s, 4);
        s += __shfl_down_sync(0xffffffffu, s, 2);
        s += __shfl_down_sync(0xffffffffu, s, 1);
        if (lane == 0) av[h] = s;
    }
    __syncthreads();
    // warp-parallel top-K selection (stable: ties -> smaller index)
    if (warp == 0) {
        #pragma unroll 1
        for (int k = 0; k < NK; k++) {
            float bv = -1e38f; int bi = 0x7fffffff;
            #pragma unroll 1
            for (int h = lane; h < NHIS; h += 32) {
                float v = av[h];
                if (v > bv) { bv = v; bi = h; }
            }
            #pragma unroll
            for (int o = 16; o > 0; o >>= 1) {
                float ov = __shfl_xor_sync(0xffffffffu, bv, o);
                int   oi = __shfl_xor_sync(0xffffffffu, bi, o);
                if (ov > bv || (ov == bv && oi < bi)) { bv = ov; bi = oi; }
            }
            if (lane == 0) {
                av[bi] = -1e38f;
                g_sel[bc*NK + k] = his_id[b*NHIS + bi];
            }
            __syncwarp();
        }
    }
}

// ================= Kernel B: fusion batched GEMM ====================
// fusion[bc,k,l,s,t] = sum_f cdd[s,l,f] * his[t,l,f] / sqrt(F)
// stored [n=bc][l][k][s][t] (conv1 NCDHW: channel=l, depth=k)
// FCP = 53 (odd) -> compute-phase row strides are odd*53 mod 32, killing the
// 2-way bank conflicts that FCP=52 produced.
#define FC 50
#define FCP 53
__global__ void fusion_kernel(const int* __restrict__ cdd_id,
                              const float* __restrict__ emb)
{
    int k  = blockIdx.x;
    int bc = blockIdx.y;
    const float* arow = emb + cdd_id[bc] * NEMB;
    const float* brow = emb + g_sel[bc*NK + k] * NEMB;

    __shared__ float As[NL*NS*FCP];
    __shared__ float Bs[NL*NS*FCP];

    int tid = threadIdx.x;
    int l = tid / 25, q = tid % 25;
    int st = (q / 5) * 4, tt = (q % 5) * 4;

    float acc[16];
    #pragma unroll
    for (int i = 0; i < 16; i++) acc[i] = 0.f;

    #pragma unroll 1
    for (int fc = 0; fc < NF; fc += FC) {
        #pragma unroll 1
        for (int idx = tid; idx < NL*NS*FC; idx += 128) {
            int ll = idx / (NS*FC);
            int r  = idx % (NS*FC);
            int s  = r / FC;
            int f  = r % FC;
            int off = s*(NL*NF) + ll*NF + fc + f;
            As[(ll*NS + s)*FCP + f] = arow[off];
            Bs[(ll*NS + s)*FCP + f] = brow[off];
        }
        __syncthreads();
        if (tid < 75) {
            const float* ap = &As[(l*NS + st)*FCP];
            const float* bp = &Bs[(l*NS + tt)*FCP];
            #pragma unroll 2
            for (int f = 0; f < FC; f++) {
                float a0 = ap[f], a1 = ap[FCP + f];
                float a2 = ap[2*FCP + f], a3 = ap[3*FCP + f];
                float b0 = bp[f], b1 = bp[FCP + f];
                float b2 = bp[2*FCP + f], b3 = bp[3*FCP + f];
                acc[0]  = fmaf(a0,b0,acc[0]);  acc[1]  = fmaf(a0,b1,acc[1]);
                acc[2]  = fmaf(a0,b2,acc[2]);  acc[3]  = fmaf(a0,b3,acc[3]);
                acc[4]  = fmaf(a1,b0,acc[4]);  acc[5]  = fmaf(a1,b1,acc[5]);
                acc[6]  = fmaf(a1,b2,acc[6]);  acc[7]  = fmaf(a1,b3,acc[7]);
                acc[8]  = fmaf(a2,b0,acc[8]);  acc[9]  = fmaf(a2,b1,acc[9]);
                acc[10] = fmaf(a2,b2,acc[10]); acc[11] = fmaf(a2,b3,acc[11]);
                acc[12] = fmaf(a3,b0,acc[12]); acc[13] = fmaf(a3,b1,acc[13]);
                acc[14] = fmaf(a3,b2,acc[14]); acc[15] = fmaf(a3,b3,acc[15]);
            }
        }
        __syncthreads();
    }
    if (tid < 75) {
        const float inv = 0.08164965809277261f;  // 1/sqrt(150)
        float* out = g_fusion + ((bc*NL + l)*NK + k)*(NS*NS);
        #pragma unroll 1
        for (int i = 0; i < 4; i++)
            #pragma unroll 1
            for (int j = 0; j < 4; j++)
                out[(st+i)*NS + (tt+j)] = acc[i*4+j] * inv;
    }
}

// ============ Kernel C: conv1(3->32,3^3,pad1)+bias+ReLU+maxpool3 ============
// in  g_fusion [n][3][18][20][20] -> out g_pool1 [n][32][6][6][6]
// Two launches (od_base 0/3) so ncu's capture slot lands on it.
// 576 thr = 16 oc-pairs x 36 pooled (oh,ow); 2 oc per thread.
// Packed fma.rn.f32x2 over the oc pair: -32% issue slots vs scalar.
__global__ void conv1_pool_kernel(const float* __restrict__ w1,
                                  const float* __restrict__ b1,
                                  int od_base)
{
    int od = od_base + blockIdx.x;   // 0..2 or 3..5
    int n  = blockIdx.y;             // 0..159

    __shared__ float in_s[5*3*22*22];             // zero halo; d halo = zero slabs
    __shared__ __align__(16) float ws2[81*32];    // [tap tf=ic*27+kd*9+t][oc]
    __shared__ float bs[32];

    int tid = threadIdx.x;

    #pragma unroll 1
    for (int i = tid; i < 5*3*22*22; i += 576) in_s[i] = 0.f;
    #pragma unroll 1
    for (int i = tid; i < 32*81; i += 576) {
        int oc = i / 81, tf = i % 81;
        ws2[tf*32 + oc] = w1[i];
    }
    if (tid < 32) bs[tid] = b1[tid];
    __syncthreads();

    #pragma unroll 1
    for (int idx = tid; idx < 5*3*400; idx += 576) {
        int slab = idx / 1200;
        int r    = idx % 1200;
        int ic   = r / 400;
        int p    = r % 400;
        int d    = od*3 - 1 + slab;
        if (d >= 0 && d < 18)
            in_s[((slab*3 + ic)*22 + 1 + p/20)*22 + 1 + p%20] =
                g_fusion[((n*3 + ic)*18 + d)*400 + p];
    }
    __syncthreads();

    int op  = tid / 36;         // 0..15
    int pos = tid % 36;
    int oh  = pos / 6, ow = pos % 6;
    int oc0 = op*2;

    float m0 = 0.f, m1 = 0.f;   // relu outputs >= 0

    #pragma unroll 1
    for (int dd = 0; dd < 3; dd++) {
        u64t acc2[9];
        #pragma unroll
        for (int i = 0; i < 9; i++) acc2[i] = 0ULL;

        #pragma unroll 1
        for (int ic = 0; ic < 3; ic++) {
            #pragma unroll 1
            for (int kd = 0; kd < 3; kd++) {
                const float* base = &in_s[(((dd + kd)*3 + ic)*22 + oh*3)*22 + ow*3];
                u64t pv[25];
                #pragma unroll
                for (int r = 0; r < 5; r++)
                    #pragma unroll
                    for (int c = 0; c < 5; c++) {
                        float v = base[r*22 + c];
                        asm("mov.b64 %0, {%1, %1};" : "=l"(pv[r*5 + c]) : "f"(v));
                    }

                const u64t* wp = reinterpret_cast<const u64t*>(
                    &ws2[(ic*27 + kd*9)*32 + oc0]);
                u64t wv[9];
                #pragma unroll
                for (int t = 0; t < 9; t++) wv[t] = wp[t*16];  // stride 32 floats

                #pragma unroll
                for (int hh = 0; hh < 3; hh++)
                    #pragma unroll
                    for (int ww = 0; ww < 3; ww++) {
                        u64t s = acc2[hh*3 + ww];
                        #pragma unroll
                        for (int kh = 0; kh < 3; kh++)
                            #pragma unroll
                            for (int kw = 0; kw < 3; kw++)
                                asm("fma.rn.f32x2 %0, %1, %2, %3;"
                                    : "=l"(s)
                                    : "l"(wv[kh*3 + kw]),
                                      "l"(pv[(hh+kh)*5 + (ww+kw)]),
                                      "l"(s));
                        acc2[hh*3 + ww] = s;
                    }
            }
        }
        float b0v = bs[oc0], b1v = bs[oc0 + 1];
        #pragma unroll
        for (int i = 0; i < 9; i++) {
            float v0, v1;
            asm("mov.b64 {%0, %1}, %2;" : "=f"(v0), "=f"(v1) : "l"(acc2[i]));
            v0 += b0v; if (v0 < 0.f) v0 = 0.f; if (v0 > m0) m0 = v0;
            v1 += b1v; if (v1 < 0.f) v1 = 0.f; if (v1 > m1) m1 = v1;
        }
    }
    g_pool1[((n*32 + oc0)*6 + od)*36 + oh*6 + ow]     = m0;
    g_pool1[((n*32 + oc0 + 1)*6 + od)*36 + oh*6 + ow] = m1;
}

// ============ Kernel D: conv2(32->16)+bias+ReLU+maxpool3 ============
// in g_pool1 [n][32][6][6][6] -> out g_feat [n][128]
// grid (2 ocg, n); 576 thr = 8oc x 8pos x 3dd x 3icp (ic split 3-way).
// Conflict-free padded smem; partials combined via psum.
#define D_STR 68
#define W_STR 872
__global__ void conv2_pool_kernel(const float* __restrict__ w2,
                                  const float* __restrict__ b2)
{
    int ocg = blockIdx.x;    // 0..1
    int n   = blockIdx.y;    // 0..159

    __shared__ float in2[32*6*D_STR];   // [ic][d] slabs of 8x8 (h,w halo), pad 4
    __shared__ float wsm[8*W_STR];      // [ocl] stride 872 (= 864 + 8 pad)
    __shared__ float psum[2*192*9];     // partials from icp 0,1
    __shared__ float red[192];
    int tid = threadIdx.x;              // 576

    #pragma unroll 1
    for (int i = tid; i < 32*6*D_STR; i += 576) in2[i] = 0.f;
    #pragma unroll 1
    for (int i = tid; i < 8*864; i += 576) {
        int ocl = i / 864;
        int r   = i % 864;
        wsm[ocl*W_STR + r] = w2[(ocg*8 + ocl)*864 + r];
    }
    __syncthreads();
    #pragma unroll 1
    for (int idx = tid; idx < 32*216; idx += 576) {
        int ic = idx / 216;
        int r  = idx % 216;
        int d  = r / 36;
        int h  = (r % 36) / 6;
        int w  = r % 6;
        in2[(ic*6 + d)*D_STR + (h + 1)*8 + w + 1] = g_pool1[n*32*216 + idx];
    }
    __syncthreads();

    // tid = t3*3 + icp ; t3 = t4*3 + dd ; t4 = ocl*8 + pos
    int icp = tid % 3;
    int t3  = tid / 3;          // 0..191
    int dd  = t3 % 3;
    int t4  = t3 / 3;           // 0..63
    int pos = t4 & 7;
    int ocl = t4 >> 3;          // 0..7
    int od  = (pos >> 2) & 1, oh = (pos >> 1) & 1, ow = pos & 1;

    float acc[9];
    #pragma unroll
    for (int i = 0; i < 9; i++) acc[i] = 0.f;

    #pragma unroll 1
    for (int ic = icp; ic < 32; ic += 3) {
        #pragma unroll 1
        for (int kd = 0; kd < 3; kd++) {
            int d = od*3 + dd + kd - 1;
            if (d < 0 || d > 5) continue;
            const float* wbase = &wsm[ocl*W_STR + ic*27 + kd*9];
            float wr[9];
            #pragma unroll
            for (int t = 0; t < 9; t++) wr[t] = wbase[t];
            const float* base = &in2[(ic*6 + d)*D_STR + (oh*3)*8 + ow*3];
            float p[25];
            #pragma unroll
            for (int r = 0; r < 5; r++)
                #pragma unroll
                for (int c = 0; c < 5; c++)
                    p[r*5 + c] = base[r*8 + c];
            #pragma unroll
            for (int hh = 0; hh < 3; hh++)
                #pragma unroll
                for (int ww = 0; ww < 3; ww++) {
                    float s = acc[hh*3 + ww];
                    #pragma unroll
                    for (int kh = 0; kh < 3; kh++)
                        #pragma unroll
                        for (int kw = 0; kw < 3; kw++)
                            s = fmaf(wr[kh*3 + kw], p[(hh+kh)*5 + (ww+kw)], s);
                    acc[hh*3 + ww] = s;
                }
        }
    }

    if (icp < 2) {
        #pragma unroll
        for (int i = 0; i < 9; i++) psum[(icp*192 + t3)*9 + i] = acc[i];
    }
    __syncthreads();
    if (icp == 2) {
        float bias = b2[ocg*8 + ocl];
        float m = 0.f;
        #pragma unroll
        for (int i = 0; i < 9; i++) {
            float v = acc[i] + psum[t3*9 + i] + psum[(192 + t3)*9 + i] + bias;
            if (v < 0.f) v = 0.f;
            if (v > m) m = v;
        }
        red[t3] = m;
    }
    __syncthreads();
    if (icp == 2 && dd == 0) {
        float f = red[t3];
        if (red[t3+1] > f) f = red[t3+1];
        if (red[t3+2] > f) f = red[t3+2];
        g_feat[n*128 + (ocg*8 + ocl)*8 + od*4 + oh*2 + ow] = f;
    }
}

// ============ Kernel E: LTR score + log_softmax over CDD ============
// 160 threads (5 warps). Warp-per-candidate coalesced dot products.
__global__ void score_kernel(const float* __restrict__ lw,
                             const float* __restrict__ lb,
                             float* __restrict__ out)
{
    __shared__ float lws[128];
    __shared__ float sc[NBC];
    int tid  = threadIdx.x;
    int warp = tid >> 5, lane = tid & 31;
    if (tid < 128) lws[tid] = lw[tid];
    __syncthreads();

    #pragma unroll 1
    for (int c = warp; c < NBC; c += 5) {
        const float* f = g_feat + c*128;
        float s = 0.f;
        #pragma unroll
        for (int j = 0; j < 4; j++)
            s = fmaf(f[j*32 + lane], lws[j*32 + lane], s);
        s += __shfl_down_sync(0xffffffffu, s, 16);
        s += __shfl_down_sync(0xffffffffu, s, 8);
        s += __shfl_down_sync(0xffffffffu, s, 4);
        s += __shfl_down_sync(0xffffffffu, s, 2);
        s += __shfl_down_sync(0xffffffffu, s, 1);
        if (lane == 0) sc[c] = s + lb[0];
    }
    __syncthreads();

    if (tid < NBC) {
        int b = tid / NCDD;
        float m = -1e38f;
        #pragma unroll 1
        for (int c = 0; c < NCDD; c++) { float v = sc[b*NCDD + c]; if (v > m) m = v; }
        float sum = 0.f;
        #pragma unroll 1
        for (int c = 0; c < NCDD; c++) sum += expf(sc[b*NCDD + c] - m);
        out[tid] = sc[tid] - m - logf(sum);
    }
}

// =================================================================
extern "C" void kernel_launch(void* const* d_in, const int* in_sizes, int n_in,
                              void* d_out, int out_size)
{
    const int*   cdd_id = (const int*)d_in[0];
    const int*   his_id = (const int*)d_in[1];
    const float* repr   = (const float*)d_in[2];
    const float* emb    = (const float*)d_in[3];
    const float* w1     = (const float*)d_in[4];
    const float* b1     = (const float*)d_in[5];
    const float* w2     = (const float*)d_in[6];
    const float* b2     = (const float*)d_in[7];
    const float* lw     = (const float*)d_in[8];
    const float* lb     = (const float*)d_in[9];

    attn_topk_kernel<<<NBC, 128>>>(cdd_id, his_id, repr);
    fusion_kernel<<<dim3(NK, NBC), 128>>>(cdd_id, emb);
    conv1_pool_kernel<<<dim3(3, NBC), 576>>>(w1, b1, 0);
    conv1_pool_kernel<<<dim3(3, NBC), 576>>>(w1, b1, 3);
    conv2_pool_kernel<<<dim3(2, NBC), 576>>>(w2, b2);
    score_kernel<<<1, NBC>>>(lw, lb, (float*)d_out);
}

// round 16
// speedup vs baseline: 1.3232x; 1.0962x over previous
#include <cuda_runtime.h>

#define NB   32
#define NCDD 5
#define NHIS 100
#define NS   20
#define NL   3
#define NF   150
#define NK   18
#define NRD  256
#define NBC  (NB*NCDD)        // 160
#define NEMB (NS*NL*NF)       // 9000

typedef unsigned long long u64t;

// ---------------- scratch (no device allocs allowed) ----------------
__device__ int   g_sel[NBC*NK];                 // selected news ids (topk order)
__device__ float g_attn[NBC*NHIS];              // attention scores
__device__ float g_fusion[NBC*NL*NK*NS*NS];     // [n][l][k][s][t]
__device__ float g_pool1[NBC*32*6*6*6];         // [n][oc][d][h][w]
__device__ float g_feat[NBC*128];               // [n][oc*8+od*4+oh*2+ow]

// ================= Kernel A1: attention dots ====================
__global__ void attn_dots_kernel(const int* __restrict__ cdd_id,
                                 const int* __restrict__ his_id,
                                 const float* __restrict__ repr)
{
    int bc = blockIdx.x;
    int b  = bc / NCDD;
    __shared__ float cv[NRD];
    int tid = threadIdx.x;
    const float* crow = repr + cdd_id[bc] * NRD;
    #pragma unroll 1
    for (int i = tid; i < NRD; i += 128) cv[i] = crow[i];
    __syncthreads();
    int warp = tid >> 5, lane = tid & 31;
    #pragma unroll 1
    for (int h = warp; h < NHIS; h += 4) {
        const float* hrow = repr + his_id[b*NHIS + h] * NRD;
        float s = 0.f;
        #pragma unroll 1
        for (int j = lane; j < NRD; j += 32) s += cv[j] * hrow[j];
        s += __shfl_down_sync(0xffffffffu, s, 16);
        s += __shfl_down_sync(0xffffffffu, s, 8);
        s += __shfl_down_sync(0xffffffffu, s, 4);
        s += __shfl_down_sync(0xffffffffu, s, 2);
        s += __shfl_down_sync(0xffffffffu, s, 1);
        if (lane == 0) g_attn[bc*NHIS + h] = s;
    }
}

// ================= Kernel A2: top-K select ====================
// one warp per bc; stable argsort(-attn) semantics (ties -> smaller index)
__global__ void attn_topk_kernel(const int* __restrict__ his_id)
{
    int bc = blockIdx.x;
    int b  = bc / NCDD;
    int lane = threadIdx.x;
    __shared__ float av[NHIS];
    #pragma unroll 1
    for (int h = lane; h < NHIS; h += 32) av[h] = g_attn[bc*NHIS + h];
    __syncwarp();
    #pragma unroll 1
    for (int k = 0; k < NK; k++) {
        float bv = -1e38f; int bi = 0x7fffffff;
        #pragma unroll 1
        for (int h = lane; h < NHIS; h += 32) {
            float v = av[h];
            if (v > bv) { bv = v; bi = h; }
        }
        #pragma unroll
        for (int o = 16; o > 0; o >>= 1) {
            float ov = __shfl_xor_sync(0xffffffffu, bv, o);
            int   oi = __shfl_xor_sync(0xffffffffu, bi, o);
            if (ov > bv || (ov == bv && oi < bi)) { bv = ov; bi = oi; }
        }
        if (lane == 0) {
            av[bi] = -1e38f;
            g_sel[bc*NK + k] = his_id[b*NHIS + bi];
        }
        __syncwarp();
    }
}

// ================= Kernel B: fusion batched GEMM ====================
// fusion[bc,k,l,s,t] = sum_f cdd[s,l,f] * his[t,l,f] / sqrt(F)
// stored [n=bc][l][k][s][t] (conv1 NCDHW: channel=l, depth=k)
// FCP = 53 (odd): conflict-free compute strides. Load phase: float2 gather,
// manual 2-way batch (stride 256) -> 4 LDGs in flight, no unroll pragma on
// the dynamic loop (cicc segfault trigger).
#define FC 50
#define FCP 53
__global__ void fusion_kernel(const int* __restrict__ cdd_id,
                              const float* __restrict__ emb,
                              int bc_base)
{
    int k  = blockIdx.x;
    int bc = bc_base + blockIdx.y;
    const float2* arow2 = reinterpret_cast<const float2*>(emb + cdd_id[bc] * NEMB);
    const float2* brow2 = reinterpret_cast<const float2*>(emb + g_sel[bc*NK + k] * NEMB);

    __shared__ float As[NL*NS*FCP];
    __shared__ float Bs[NL*NS*FCP];

    int tid = threadIdx.x;
    int l = tid / 25, q = tid % 25;
    int st = (q / 5) * 4, tt = (q % 5) * 4;

    float acc[16];
    #pragma unroll
    for (int i = 0; i < 16; i++) acc[i] = 0.f;

    #pragma unroll 1
    for (int fc2 = 0; fc2 < 75; fc2 += 25) {   // float2 chunk base: f = 2*fc2
        // load 1500 float2 per tile, two elements per iteration (MLP 4)
        #pragma unroll 1
        for (int j0 = tid; j0 < NL*NS*25; j0 += 256) {
            int j1 = j0 + 128;
            int s0  = j0 / 75, r0 = j0 % 75;
            int ll0 = r0 / 25, fp0 = r0 % 25;
            int gi0 = s0*225 + ll0*75 + fc2 + fp0;
            float2 va0 = arow2[gi0];
            float2 vb0 = brow2[gi0];
            float2 va1, vb1;
            int so1 = 0;
            if (j1 < NL*NS*25) {
                int s1  = j1 / 75, r1 = j1 % 75;
                int ll1 = r1 / 25, fp1 = r1 % 25;
                int gi1 = s1*225 + ll1*75 + fc2 + fp1;
                va1 = arow2[gi1];
                vb1 = brow2[gi1];
                so1 = (ll1*NS + s1)*FCP + 2*fp1;
            }
            int so0 = (ll0*NS + s0)*FCP + 2*fp0;
            As[so0]     = va0.x;
            As[so0 + 1] = va0.y;
            Bs[so0]     = vb0.x;
            Bs[so0 + 1] = vb0.y;
            if (j1 < NL*NS*25) {
                As[so1]     = va1.x;
                As[so1 + 1] = va1.y;
                Bs[so1]     = vb1.x;
                Bs[so1 + 1] = vb1.y;
            }
        }
        __syncthreads();
        if (tid < 75) {
            const float* ap = &As[(l*NS + st)*FCP];
            const float* bp = &Bs[(l*NS + tt)*FCP];
            #pragma unroll 2
            for (int f = 0; f < FC; f++) {
                float a0 = ap[f], a1 = ap[FCP + f];
                float a2 = ap[2*FCP + f], a3 = ap[3*FCP + f];
                float b0 = bp[f], b1 = bp[FCP + f];
                float b2 = bp[2*FCP + f], b3 = bp[3*FCP + f];
                acc[0]  = fmaf(a0,b0,acc[0]);  acc[1]  = fmaf(a0,b1,acc[1]);
                acc[2]  = fmaf(a0,b2,acc[2]);  acc[3]  = fmaf(a0,b3,acc[3]);
                acc[4]  = fmaf(a1,b0,acc[4]);  acc[5]  = fmaf(a1,b1,acc[5]);
                acc[6]  = fmaf(a1,b2,acc[6]);  acc[7]  = fmaf(a1,b3,acc[7]);
                acc[8]  = fmaf(a2,b0,acc[8]);  acc[9]  = fmaf(a2,b1,acc[9]);
                acc[10] = fmaf(a2,b2,acc[10]); acc[11] = fmaf(a2,b3,acc[11]);
                acc[12] = fmaf(a3,b0,acc[12]); acc[13] = fmaf(a3,b1,acc[13]);
                acc[14] = fmaf(a3,b2,acc[14]); acc[15] = fmaf(a3,b3,acc[15]);
            }
        }
        __syncthreads();
    }
    if (tid < 75) {
        const float inv = 0.08164965809277261f;  // 1/sqrt(150)
        float* out = g_fusion + ((bc*NL + l)*NK + k)*(NS*NS);
        #pragma unroll 1
        for (int i = 0; i < 4; i++)
            #pragma unroll 1
            for (int j = 0; j < 4; j++)
                out[(st+i)*NS + (tt+j)] = acc[i*4+j] * inv;
    }
}

// ============ Kernel C: conv1(3->32,3^3,pad1)+bias+ReLU+maxpool3 ============
// in  g_fusion [n][3][18][20][20] -> out g_pool1 [n][32][6][6][6]
// 576 thr = 16 oc-pairs x 36 pooled (oh,ow); 2 oc per thread.
// Packed fma.rn.f32x2 over the oc pair.
__global__ void conv1_pool_kernel(const float* __restrict__ w1,
                                  const float* __restrict__ b1)
{
    int od = blockIdx.x;   // 0..5
    int n  = blockIdx.y;   // 0..159

    __shared__ float in_s[5*3*22*22];             // zero halo; d halo = zero slabs
    __shared__ __align__(16) float ws2[81*32];    // [tap tf=ic*27+kd*9+t][oc]
    __shared__ float bs[32];

    int tid = threadIdx.x;

    #pragma unroll 1
    for (int i = tid; i < 5*3*22*22; i += 576) in_s[i] = 0.f;
    #pragma unroll 1
    for (int i = tid; i < 32*81; i += 576) {
        int oc = i / 81, tf = i % 81;
        ws2[tf*32 + oc] = w1[i];
    }
    if (tid < 32) bs[tid] = b1[tid];
    __syncthreads();

    #pragma unroll 1
    for (int idx = tid; idx < 5*3*400; idx += 576) {
        int slab = idx / 1200;
        int r    = idx % 1200;
        int ic   = r / 400;
        int p    = r % 400;
        int d    = od*3 - 1 + slab;
        if (d >= 0 && d < 18)
            in_s[((slab*3 + ic)*22 + 1 + p/20)*22 + 1 + p%20] =
                g_fusion[((n*3 + ic)*18 + d)*400 + p];
    }
    __syncthreads();

    int op  = tid / 36;         // 0..15
    int pos = tid % 36;
    int oh  = pos / 6, ow = pos % 6;
    int oc0 = op*2;

    float m0 = 0.f, m1 = 0.f;   // relu outputs >= 0

    #pragma unroll 1
    for (int dd = 0; dd < 3; dd++) {
        u64t acc2[9];
        #pragma unroll
        for (int i = 0; i < 9; i++) acc2[i] = 0ULL;

        #pragma unroll 1
        for (int ic = 0; ic < 3; ic++) {
            #pragma unroll 1
            for (int kd = 0; kd < 3; kd++) {
                const float* base = &in_s[(((dd + kd)*3 + ic)*22 + oh*3)*22 + ow*3];
                u64t pv[25];
                #pragma unroll
                for (int r = 0; r < 5; r++)
                    #pragma unroll
                    for (int c = 0; c < 5; c++) {
                        float v = base[r*22 + c];
                        asm("mov.b64 %0, {%1, %1};" : "=l"(pv[r*5 + c]) : "f"(v));
                    }

                const u64t* wp = reinterpret_cast<const u64t*>(
                    &ws2[(ic*27 + kd*9)*32 + oc0]);
                u64t wv[9];
                #pragma unroll
                for (int t = 0; t < 9; t++) wv[t] = wp[t*16];  // stride 32 floats

                #pragma unroll
                for (int hh = 0; hh < 3; hh++)
                    #pragma unroll
                    for (int ww = 0; ww < 3; ww++) {
                        u64t s = acc2[hh*3 + ww];
                        #pragma unroll
                        for (int kh = 0; kh < 3; kh++)
                            #pragma unroll
                            for (int kw = 0; kw < 3; kw++)
                                asm("fma.rn.f32x2 %0, %1, %2, %3;"
                                    : "=l"(s)
                                    : "l"(wv[kh*3 + kw]),
                                      "l"(pv[(hh+kh)*5 + (ww+kw)]),
                                      "l"(s));
                        acc2[hh*3 + ww] = s;
                    }
            }
        }
        float b0v = bs[oc0], b1v = bs[oc0 + 1];
        #pragma unroll
        for (int i = 0; i < 9; i++) {
            float v0, v1;
            asm("mov.b64 {%0, %1}, %2;" : "=f"(v0), "=f"(v1) : "l"(acc2[i]));
            v0 += b0v; if (v0 < 0.f) v0 = 0.f; if (v0 > m0) m0 = v0;
            v1 += b1v; if (v1 < 0.f) v1 = 0.f; if (v1 > m1) m1 = v1;
        }
    }
    g_pool1[((n*32 + oc0)*6 + od)*36 + oh*6 + ow]     = m0;
    g_pool1[((n*32 + oc0 + 1)*6 + od)*36 + oh*6 + ow] = m1;
}

// ============ Kernel D: conv2(32->16)+bias+ReLU+maxpool3 ============
// in g_pool1 [n][32][6][6][6] -> out g_feat [n][128]
// grid (2 ocg, n); 576 thr = 8oc x 8pos x 3dd x 3icp (ic split 3-way).
// Conflict-free padded smem; partials combined via psum.
#define D_STR 68
#define W_STR 872
__global__ void conv2_pool_kernel(const float* __restrict__ w2,
                                  const float* __restrict__ b2)
{
    int ocg = blockIdx.x;    // 0..1
    int n   = blockIdx.y;    // 0..159

    __shared__ float in2[32*6*D_STR];   // [ic][d] slabs of 8x8 (h,w halo), pad 4
    __shared__ float wsm[8*W_STR];      // [ocl] stride 872 (= 864 + 8 pad)
    __shared__ float psum[2*192*9];     // partials from icp 0,1
    __shared__ float red[192];
    int tid = threadIdx.x;              // 576

    #pragma unroll 1
    for (int i = tid; i < 32*6*D_STR; i += 576) in2[i] = 0.f;
    #pragma unroll 1
    for (int i = tid; i < 8*864; i += 576) {
        int ocl = i / 864;
        int r   = i % 864;
        wsm[ocl*W_STR + r] = w2[(ocg*8 + ocl)*864 + r];
    }
    __syncthreads();
    #pragma unroll 1
    for (int idx = tid; idx < 32*216; idx += 576) {
        int ic = idx / 216;
        int r  = idx % 216;
        int d  = r / 36;
        int h  = (r % 36) / 6;
        int w  = r % 6;
        in2[(ic*6 + d)*D_STR + (h + 1)*8 + w + 1] = g_pool1[n*32*216 + idx];
    }
    __syncthreads();

    // tid = t3*3 + icp ; t3 = t4*3 + dd ; t4 = ocl*8 + pos
    int icp = tid % 3;
    int t3  = tid / 3;          // 0..191
    int dd  = t3 % 3;
    int t4  = t3 / 3;           // 0..63
    int pos = t4 & 7;
    int ocl = t4 >> 3;          // 0..7
    int od  = (pos >> 2) & 1, oh = (pos >> 1) & 1, ow = pos & 1;

    float acc[9];
    #pragma unroll
    for (int i = 0; i < 9; i++) acc[i] = 0.f;

    #pragma unroll 1
    for (int ic = icp; ic < 32; ic += 3) {
        #pragma unroll 1
        for (int kd = 0; kd < 3; kd++) {
            int d = od*3 + dd + kd - 1;
            if (d < 0 || d > 5) continue;
            const float* wbase = &wsm[ocl*W_STR + ic*27 + kd*9];
            float wr[9];
            #pragma unroll
            for (int t = 0; t < 9; t++) wr[t] = wbase[t];
            const float* base = &in2[(ic*6 + d)*D_STR + (oh*3)*8 + ow*3];
            float p[25];
            #pragma unroll
            for (int r = 0; r < 5; r++)
                #pragma unroll
                for (int c = 0; c < 5; c++)
                    p[r*5 + c] = base[r*8 + c];
            #pragma unroll
            for (int hh = 0; hh < 3; hh++)
                #pragma unroll
                for (int ww = 0; ww < 3; ww++) {
                    float s = acc[hh*3 + ww];
                    #pragma unroll
                    for (int kh = 0; kh < 3; kh++)
                        #pragma unroll
                        for (int kw = 0; kw < 3; kw++)
                            s = fmaf(wr[kh*3 + kw], p[(hh+kh)*5 + (ww+kw)], s);
                    acc[hh*3 + ww] = s;
                }
        }
    }

    if (icp < 2) {
        #pragma unroll
        for (int i = 0; i < 9; i++) psum[(icp*192 + t3)*9 + i] = acc[i];
    }
    __syncthreads();
    if (icp == 2) {
        float bias = b2[ocg*8 + ocl];
        float m = 0.f;
        #pragma unroll
        for (int i = 0; i < 9; i++) {
            float v = acc[i] + psum[t3*9 + i] + psum[(192 + t3)*9 + i] + bias;
            if (v < 0.f) v = 0.f;
            if (v > m) m = v;
        }
        red[t3] = m;
    }
    __syncthreads();
    if (icp == 2 && dd == 0) {
        float f = red[t3];
        if (red[t3+1] > f) f = red[t3+1];
        if (red[t3+2] > f) f = red[t3+2];
        g_feat[n*128 + (ocg*8 + ocl)*8 + od*4 + oh*2 + ow] = f;
    }
}

// ============ Kernel E: LTR score + log_softmax over CDD ============
// 160 threads (5 warps). Warp-per-candidate coalesced dot products.
__global__ void score_kernel(const float* __restrict__ lw,
                             const float* __restrict__ lb,
                             float* __restrict__ out)
{
    __shared__ float lws[128];
    __shared__ float sc[NBC];
    int tid  = threadIdx.x;
    int warp = tid >> 5, lane = tid & 31;
    if (tid < 128) lws[tid] = lw[tid];
    __syncthreads();

    #pragma unroll 1
    for (int c = warp; c < NBC; c += 5) {
        const float* f = g_feat + c*128;
        float s = 0.f;
        #pragma unroll
        for (int j = 0; j < 4; j++)
            s = fmaf(f[j*32 + lane], lws[j*32 + lane], s);
        s += __shfl_down_sync(0xffffffffu, s, 16);
        s += __shfl_down_sync(0xffffffffu, s, 8);
        s += __shfl_down_sync(0xffffffffu, s, 4);
        s += __shfl_down_sync(0xffffffffu, s, 2);
        s += __shfl_down_sync(0xffffffffu, s, 1);
        if (lane == 0) sc[c] = s + lb[0];
    }
    __syncthreads();

    if (tid < NBC) {
        int b = tid / NCDD;
        float m = -1e38f;
        #pragma unroll 1
        for (int c = 0; c < NCDD; c++) { float v = sc[b*NCDD + c]; if (v > m) m = v; }
        float sum = 0.f;
        #pragma unroll 1
        for (int c = 0; c < NCDD; c++) sum += expf(sc[b*NCDD + c] - m);
        out[tid] = sc[tid] - m - logf(sum);
    }
}

// =================================================================
extern "C" void kernel_launch(void* const* d_in, const int* in_sizes, int n_in,
                              void* d_out, int out_size)
{
    const int*   cdd_id = (const int*)d_in[0];
    const int*   his_id = (const int*)d_in[1];
    const float* repr   = (const float*)d_in[2];
    const float* emb    = (const float*)d_in[3];
    const float* w1     = (const float*)d_in[4];
    const float* b1     = (const float*)d_in[5];
    const float* w2     = (const float*)d_in[6];
    const float* b2     = (const float*)d_in[7];
    const float* lw     = (const float*)d_in[8];
    const float* lb     = (const float*)d_in[9];

    attn_dots_kernel<<<NBC, 128>>>(cdd_id, his_id, repr);      // #1
    attn_topk_kernel<<<NBC, 32>>>(his_id);                     // #2
    fusion_kernel<<<dim3(NK, 80), 128>>>(cdd_id, emb, 0);      // #3
    fusion_kernel<<<dim3(NK, 80), 128>>>(cdd_id, emb, 80);     // #4  <- ncu capture slot
    conv1_pool_kernel<<<dim3(6, NBC), 576>>>(w1, b1);          // #5
    conv2_pool_kernel<<<dim3(2, NBC), 576>>>(w2, b2);          // #6
    score_kernel<<<1, NBC>>>(lw, lb, (float*)d_out);           // #7
}

// round 17
// speedup vs baseline: 1.4008x; 1.0587x over previous
#include <cuda_runtime.h>

#define NB   32
#define NCDD 5
#define NHIS 100
#define NS   20
#define NL   3
#define NF   150
#define NK   18
#define NRD  256
#define NBC  (NB*NCDD)        // 160
#define NEMB (NS*NL*NF)       // 9000

typedef unsigned long long u64t;

// ---------------- scratch (no device allocs allowed) ----------------
__device__ int   g_sel[NBC*NK];                 // selected news ids (topk order)
__device__ float g_attn[NBC*NHIS];              // attention scores
__device__ float g_fusion[NBC*NL*NK*NS*NS];     // [n][l][k][s][t]
__device__ float g_pool1[NBC*32*6*6*6];         // [n][oc][d][h][w]
__device__ float g_feat[NBC*128];               // [n][oc*8+od*4+oh*2+ow]

// ================= Kernel A1: attention dots ====================
__global__ void attn_dots_kernel(const int* __restrict__ cdd_id,
                                 const int* __restrict__ his_id,
                                 const float* __restrict__ repr)
{
    int bc = blockIdx.x;
    int b  = bc / NCDD;
    __shared__ float cv[NRD];
    int tid = threadIdx.x;
    const float* crow = repr + cdd_id[bc] * NRD;
    #pragma unroll 1
    for (int i = tid; i < NRD; i += 128) cv[i] = crow[i];
    __syncthreads();
    int warp = tid >> 5, lane = tid & 31;
    #pragma unroll 1
    for (int h = warp; h < NHIS; h += 4) {
        const float* hrow = repr + his_id[b*NHIS + h] * NRD;
        float s = 0.f;
        #pragma unroll 1
        for (int j = lane; j < NRD; j += 32) s += cv[j] * hrow[j];
        s += __shfl_down_sync(0xffffffffu, s, 16);
        s += __shfl_down_sync(0xffffffffu, s, 8);
        s += __shfl_down_sync(0xffffffffu, s, 4);
        s += __shfl_down_sync(0xffffffffu, s, 2);
        s += __shfl_down_sync(0xffffffffu, s, 1);
        if (lane == 0) g_attn[bc*NHIS + h] = s;
    }
}

// ================= Kernel A2: top-K select ====================
// one warp per bc; stable argsort(-attn) semantics (ties -> smaller index)
__global__ void attn_topk_kernel(const int* __restrict__ his_id)
{
    int bc = blockIdx.x;
    int b  = bc / NCDD;
    int lane = threadIdx.x;
    __shared__ float av[NHIS];
    #pragma unroll 1
    for (int h = lane; h < NHIS; h += 32) av[h] = g_attn[bc*NHIS + h];
    __syncwarp();
    #pragma unroll 1
    for (int k = 0; k < NK; k++) {
        float bv = -1e38f; int bi = 0x7fffffff;
        #pragma unroll 1
        for (int h = lane; h < NHIS; h += 32) {
            float v = av[h];
            if (v > bv) { bv = v; bi = h; }
        }
        #pragma unroll
        for (int o = 16; o > 0; o >>= 1) {
            float ov = __shfl_xor_sync(0xffffffffu, bv, o);
            int   oi = __shfl_xor_sync(0xffffffffu, bi, o);
            if (ov > bv || (ov == bv && oi < bi)) { bv = ov; bi = oi; }
        }
        if (lane == 0) {
            av[bi] = -1e38f;
            g_sel[bc*NK + k] = his_id[b*NHIS + bi];
        }
        __syncwarp();
    }
}

// ================= Kernel B: fusion batched GEMM ====================
// fusion[bc,k,l,s,t] = sum_f cdd[s,l,f] * his[t,l,f] / sqrt(F)
// stored [n=bc][l][k][s][t] (conv1 NCDHW: channel=l, depth=k)
// Block handles TWO k values sharing the A tile. Smem layout [l][f][s],
// row stride SP=20 (16B-aligned) -> compute reads are 2x LDS.128 per 16 FMA.
// 160 threads: 150 compute (75 per k). No unroll pragmas on dynamic loops.
#define FC 50
#define SP 20
__global__ void fusion_kernel(const int* __restrict__ cdd_id,
                              const float* __restrict__ emb,
                              int bc_base)
{
    int kk = blockIdx.x;             // 0..8
    int bc = bc_base + blockIdx.y;
    int k0 = kk*2;
    const float2* arow2 = reinterpret_cast<const float2*>(emb + cdd_id[bc] * NEMB);
    const float2* b0row = reinterpret_cast<const float2*>(emb + g_sel[bc*NK + k0] * NEMB);
    const float2* b1row = reinterpret_cast<const float2*>(emb + g_sel[bc*NK + k0 + 1] * NEMB);

    __shared__ __align__(16) float As[NL*FC*SP];      // 3000 floats
    __shared__ __align__(16) float Bs[2][NL*FC*SP];

    int tid = threadIdx.x;           // 160
    int kh  = tid / 75;              // 0,1 for tid<150
    int t75 = tid % 75;
    int l   = t75 / 25, q = t75 % 25;
    int st  = (q / 5) * 4, tt = (q % 5) * 4;

    float acc[16];
    #pragma unroll
    for (int i = 0; i < 16; i++) acc[i] = 0.f;

    #pragma unroll 1
    for (int fc2 = 0; fc2 < 75; fc2 += 25) {   // chunk: floats f in [2*fc2, 2*fc2+50)
        // load 1500 float2 per row (a, b0, b1), transposed store to [l][f][s]
        #pragma unroll 1
        for (int j = tid; j < 1500; j += 160) {
            int s  = j / 75;
            int r  = j % 75;
            int l2 = r / 25;
            int fp = r % 25;
            int gi = s*225 + l2*75 + fc2 + fp;      // global float2 index
            float2 va  = arow2[gi];
            float2 vb0 = b0row[gi];
            float2 vb1 = b1row[gi];
            int so = (l2*FC + 2*fp)*SP + s;
            As[so]        = va.x;  As[so + SP]    = va.y;
            Bs[0][so]     = vb0.x; Bs[0][so + SP] = vb0.y;
            Bs[1][so]     = vb1.x; Bs[1][so + SP] = vb1.y;
        }
        __syncthreads();
        if (tid < 150) {
            const float* ap = &As[l*FC*SP + st];
            const float* bp = &Bs[kh][l*FC*SP + tt];
            #pragma unroll 2
            for (int f = 0; f < FC; f++) {
                float4 a4 = *reinterpret_cast<const float4*>(ap + f*SP);
                float4 b4 = *reinterpret_cast<const float4*>(bp + f*SP);
                acc[0]  = fmaf(a4.x, b4.x, acc[0]);
                acc[1]  = fmaf(a4.x, b4.y, acc[1]);
                acc[2]  = fmaf(a4.x, b4.z, acc[2]);
                acc[3]  = fmaf(a4.x, b4.w, acc[3]);
                acc[4]  = fmaf(a4.y, b4.x, acc[4]);
                acc[5]  = fmaf(a4.y, b4.y, acc[5]);
                acc[6]  = fmaf(a4.y, b4.z, acc[6]);
                acc[7]  = fmaf(a4.y, b4.w, acc[7]);
                acc[8]  = fmaf(a4.z, b4.x, acc[8]);
                acc[9]  = fmaf(a4.z, b4.y, acc[9]);
                acc[10] = fmaf(a4.z, b4.z, acc[10]);
                acc[11] = fmaf(a4.z, b4.w, acc[11]);
                acc[12] = fmaf(a4.w, b4.x, acc[12]);
                acc[13] = fmaf(a4.w, b4.y, acc[13]);
                acc[14] = fmaf(a4.w, b4.z, acc[14]);
                acc[15] = fmaf(a4.w, b4.w, acc[15]);
            }
        }
        __syncthreads();
    }
    if (tid < 150) {
        const float inv = 0.08164965809277261f;  // 1/sqrt(150)
        float* out = g_fusion + ((bc*NL + l)*NK + (k0 + kh))*(NS*NS);
        #pragma unroll 1
        for (int i = 0; i < 4; i++)
            #pragma unroll 1
            for (int j = 0; j < 4; j++)
                out[(st+i)*NS + (tt+j)] = acc[i*4+j] * inv;
    }
}

// ============ Kernel C: conv1(3->32,3^3,pad1)+bias+ReLU+maxpool3 ============
// in  g_fusion [n][3][18][20][20] -> out g_pool1 [n][32][6][6][6]
// 576 thr = 16 oc-pairs x 36 pooled (oh,ow); 2 oc per thread.
// Packed fma.rn.f32x2 over the oc pair.
__global__ void conv1_pool_kernel(const float* __restrict__ w1,
                                  const float* __restrict__ b1)
{
    int od = blockIdx.x;   // 0..5
    int n  = blockIdx.y;   // 0..159

    __shared__ float in_s[5*3*22*22];             // zero halo; d halo = zero slabs
    __shared__ __align__(16) float ws2[81*32];    // [tap tf=ic*27+kd*9+t][oc]
    __shared__ float bs[32];

    int tid = threadIdx.x;

    #pragma unroll 1
    for (int i = tid; i < 5*3*22*22; i += 576) in_s[i] = 0.f;
    #pragma unroll 1
    for (int i = tid; i < 32*81; i += 576) {
        int oc = i / 81, tf = i % 81;
        ws2[tf*32 + oc] = w1[i];
    }
    if (tid < 32) bs[tid] = b1[tid];
    __syncthreads();

    #pragma unroll 1
    for (int idx = tid; idx < 5*3*400; idx += 576) {
        int slab = idx / 1200;
        int r    = idx % 1200;
        int ic   = r / 400;
        int p    = r % 400;
        int d    = od*3 - 1 + slab;
        if (d >= 0 && d < 18)
            in_s[((slab*3 + ic)*22 + 1 + p/20)*22 + 1 + p%20] =
                g_fusion[((n*3 + ic)*18 + d)*400 + p];
    }
    __syncthreads();

    int op  = tid / 36;         // 0..15
    int pos = tid % 36;
    int oh  = pos / 6, ow = pos % 6;
    int oc0 = op*2;

    float m0 = 0.f, m1 = 0.f;   // relu outputs >= 0

    #pragma unroll 1
    for (int dd = 0; dd < 3; dd++) {
        u64t acc2[9];
        #pragma unroll
        for (int i = 0; i < 9; i++) acc2[i] = 0ULL;

        #pragma unroll 1
        for (int ic = 0; ic < 3; ic++) {
            #pragma unroll 1
            for (int kd = 0; kd < 3; kd++) {
                const float* base = &in_s[(((dd + kd)*3 + ic)*22 + oh*3)*22 + ow*3];
                u64t pv[25];
                #pragma unroll
                for (int r = 0; r < 5; r++)
                    #pragma unroll
                    for (int c = 0; c < 5; c++) {
                        float v = base[r*22 + c];
                        asm("mov.b64 %0, {%1, %1};" : "=l"(pv[r*5 + c]) : "f"(v));
                    }

                const u64t* wp = reinterpret_cast<const u64t*>(
                    &ws2[(ic*27 + kd*9)*32 + oc0]);
                u64t wv[9];
                #pragma unroll
                for (int t = 0; t < 9; t++) wv[t] = wp[t*16];  // stride 32 floats

                #pragma unroll
                for (int hh = 0; hh < 3; hh++)
                    #pragma unroll
                    for (int ww = 0; ww < 3; ww++) {
                        u64t s = acc2[hh*3 + ww];
                        #pragma unroll
                        for (int kh = 0; kh < 3; kh++)
                            #pragma unroll
                            for (int kw = 0; kw < 3; kw++)
                                asm("fma.rn.f32x2 %0, %1, %2, %3;"
                                    : "=l"(s)
                                    : "l"(wv[kh*3 + kw]),
                                      "l"(pv[(hh+kh)*5 + (ww+kw)]),
                                      "l"(s));
                        acc2[hh*3 + ww] = s;
                    }
            }
        }
        float b0v = bs[oc0], b1v = bs[oc0 + 1];
        #pragma unroll
        for (int i = 0; i < 9; i++) {
            float v0, v1;
            asm("mov.b64 {%0, %1}, %2;" : "=f"(v0), "=f"(v1) : "l"(acc2[i]));
            v0 += b0v; if (v0 < 0.f) v0 = 0.f; if (v0 > m0) m0 = v0;
            v1 += b1v; if (v1 < 0.f) v1 = 0.f; if (v1 > m1) m1 = v1;
        }
    }
    g_pool1[((n*32 + oc0)*6 + od)*36 + oh*6 + ow]     = m0;
    g_pool1[((n*32 + oc0 + 1)*6 + od)*36 + oh*6 + ow] = m1;
}

// ============ Kernel D: conv2(32->16)+bias+ReLU+maxpool3 ============
// in g_pool1 [n][32][6][6][6] -> out g_feat [n][128]
// grid (2 ocg, n); 576 thr = 8oc x 8pos x 3dd x 3icp (ic split 3-way).
// Conflict-free padded smem; partials combined via psum.
#define D_STR 68
#define W_STR 872
__global__ void conv2_pool_kernel(const float* __restrict__ w2,
                                  const float* __restrict__ b2)
{
    int ocg = blockIdx.x;    // 0..1
    int n   = blockIdx.y;    // 0..159

    __shared__ float in2[32*6*D_STR];   // [ic][d] slabs of 8x8 (h,w halo), pad 4
    __shared__ float wsm[8*W_STR];      // [ocl] stride 872 (= 864 + 8 pad)
    __shared__ float psum[2*192*9];     // partials from icp 0,1
    __shared__ float red[192];
    int tid = threadIdx.x;              // 576

    #pragma unroll 1
    for (int i = tid; i < 32*6*D_STR; i += 576) in2[i] = 0.f;
    #pragma unroll 1
    for (int i = tid; i < 8*864; i += 576) {
        int ocl = i / 864;
        int r   = i % 864;
        wsm[ocl*W_STR + r] = w2[(ocg*8 + ocl)*864 + r];
    }
    __syncthreads();
    #pragma unroll 1
    for (int idx = tid; idx < 32*216; idx += 576) {
        int ic = idx / 216;
        int r  = idx % 216;
        int d  = r / 36;
        int h  = (r % 36) / 6;
        int w  = r % 6;
        in2[(ic*6 + d)*D_STR + (h + 1)*8 + w + 1] = g_pool1[n*32*216 + idx];
    }
    __syncthreads();

    // tid = t3*3 + icp ; t3 = t4*3 + dd ; t4 = ocl*8 + pos
    int icp = tid % 3;
    int t3  = tid / 3;          // 0..191
    int dd  = t3 % 3;
    int t4  = t3 / 3;           // 0..63
    int pos = t4 & 7;
    int ocl = t4 >> 3;          // 0..7
    int od  = (pos >> 2) & 1, oh = (pos >> 1) & 1, ow = pos & 1;

    float acc[9];
    #pragma unroll
    for (int i = 0; i < 9; i++) acc[i] = 0.f;

    #pragma unroll 1
    for (int ic = icp; ic < 32; ic += 3) {
        #pragma unroll 1
        for (int kd = 0; kd < 3; kd++) {
            int d = od*3 + dd + kd - 1;
            if (d < 0 || d > 5) continue;
            const float* wbase = &wsm[ocl*W_STR + ic*27 + kd*9];
            float wr[9];
            #pragma unroll
            for (int t = 0; t < 9; t++) wr[t] = wbase[t];
            const float* base = &in2[(ic*6 + d)*D_STR + (oh*3)*8 + ow*3];
            float p[25];
            #pragma unroll
            for (int r = 0; r < 5; r++)
                #pragma unroll
                for (int c = 0; c < 5; c++)
                    p[r*5 + c] = base[r*8 + c];
            #pragma unroll
            for (int hh = 0; hh < 3; hh++)
                #pragma unroll
                for (int ww = 0; ww < 3; ww++) {
                    float s = acc[hh*3 + ww];
                    #pragma unroll
                    for (int kh = 0; kh < 3; kh++)
                        #pragma unroll
                        for (int kw = 0; kw < 3; kw++)
                            s = fmaf(wr[kh*3 + kw], p[(hh+kh)*5 + (ww+kw)], s);
                    acc[hh*3 + ww] = s;
                }
        }
    }

    if (icp < 2) {
        #pragma unroll
        for (int i = 0; i < 9; i++) psum[(icp*192 + t3)*9 + i] = acc[i];
    }
    __syncthreads();
    if (icp == 2) {
        float bias = b2[ocg*8 + ocl];
        float m = 0.f;
        #pragma unroll
        for (int i = 0; i < 9; i++) {
            float v = acc[i] + psum[t3*9 + i] + psum[(192 + t3)*9 + i] + bias;
            if (v < 0.f) v = 0.f;
            if (v > m) m = v;
        }
        red[t3] = m;
    }
    __syncthreads();
    if (icp == 2 && dd == 0) {
        float f = red[t3];
        if (red[t3+1] > f) f = red[t3+1];
        if (red[t3+2] > f) f = red[t3+2];
        g_feat[n*128 + (ocg*8 + ocl)*8 + od*4 + oh*2 + ow] = f;
    }
}

// ============ Kernel E: LTR score + log_softmax over CDD ============
// 160 threads (5 warps). Warp-per-candidate coalesced dot products.
__global__ void score_kernel(const float* __restrict__ lw,
                             const float* __restrict__ lb,
                             float* __restrict__ out)
{
    __shared__ float lws[128];
    __shared__ float sc[NBC];
    int tid  = threadIdx.x;
    int warp = tid >> 5, lane = tid & 31;
    if (tid < 128) lws[tid] = lw[tid];
    __syncthreads();

    #pragma unroll 1
    for (int c = warp; c < NBC; c += 5) {
        const float* f = g_feat + c*128;
        float s = 0.f;
        #pragma unroll
        for (int j = 0; j < 4; j++)
            s = fmaf(f[j*32 + lane], lws[j*32 + lane], s);
        s += __shfl_down_sync(0xffffffffu, s, 16);
        s += __shfl_down_sync(0xffffffffu, s, 8);
        s += __shfl_down_sync(0xffffffffu, s, 4);
        s += __shfl_down_sync(0xffffffffu, s, 2);
        s += __shfl_down_sync(0xffffffffu, s, 1);
        if (lane == 0) sc[c] = s + lb[0];
    }
    __syncthreads();

    if (tid < NBC) {
        int b = tid / NCDD;
        float m = -1e38f;
        #pragma unroll 1
        for (int c = 0; c < NCDD; c++) { float v = sc[b*NCDD + c]; if (v > m) m = v; }
        float sum = 0.f;
        #pragma unroll 1
        for (int c = 0; c < NCDD; c++) sum += expf(sc[b*NCDD + c] - m);
        out[tid] = sc[tid] - m - logf(sum);
    }
}

// =================================================================
extern "C" void kernel_launch(void* const* d_in, const int* in_sizes, int n_in,
                              void* d_out, int out_size)
{
    const int*   cdd_id = (const int*)d_in[0];
    const int*   his_id = (const int*)d_in[1];
    const float* repr   = (const float*)d_in[2];
    const float* emb    = (const float*)d_in[3];
    const float* w1     = (const float*)d_in[4];
    const float* b1     = (const float*)d_in[5];
    const float* w2     = (const float*)d_in[6];
    const float* b2     = (const float*)d_in[7];
    const float* lw     = (const float*)d_in[8];
    const float* lb     = (const float*)d_in[9];

    attn_dots_kernel<<<NBC, 128>>>(cdd_id, his_id, repr);      // #1
    attn_topk_kernel<<<NBC, 32>>>(his_id);                     // #2
    fusion_kernel<<<dim3(9, 80), 160>>>(cdd_id, emb, 0);       // #3
    fusion_kernel<<<dim3(9, 80), 160>>>(cdd_id, emb, 80);      // #4  <- ncu capture slot
    conv1_pool_kernel<<<dim3(6, NBC), 576>>>(w1, b1);          // #5
    conv2_pool_kernel<<<dim3(2, NBC), 576>>>(w2, b2);          // #6
    score_kernel<<<1, NBC>>>(lw, lb, (float*)d_out);           // #7
}